// round 7
// baseline (speedup 1.0000x reference)
#include <cuda_runtime.h>
#include <cuda_fp16.h>

#define N_AG 64
#define HW 8
#define BLK 128
#define RPB 32            // rows per block (2 rows in flight x 16 iters)

__device__ __forceinline__ half2 tanh_h2(half2 x) {
    half2 y;
    asm("tanh.approx.f16x2 %0, %1;"
        : "=r"(reinterpret_cast<unsigned&>(y))
        : "r"(reinterpret_cast<unsigned const&>(x)));
    return y;
}

// fp32 tanh-pair via one f16x2 MUFU (fp32 pre-act, packed tanh)
__device__ __forceinline__ float2 tanh_pair(float a, float b) {
    return __half22float2(tanh_h2(__floats2half2_rn(a, b)));
}

// Coupling for one edge: HFMA2 pre-activation on h-paired weights, fp32 dot.
__device__ __forceinline__ float coup(half2 s2, half2 n2,
                                      const half2* A0, const half2* A1,
                                      const half2* CB, const float* CW)
{
    float cc = 0.f;
    #pragma unroll
    for (int p = 0; p < 4; p++) {
        half2 t = __hfma2(s2, A0[p], __hfma2(n2, A1[p], CB[p]));
        float2 g = __half22float2(tanh_h2(t));
        cc = fmaf(g.x, CW[2*p], fmaf(g.y, CW[2*p + 1], cc));
    }
    return cc;
}

__global__ void __launch_bounds__(BLK)
ode_kernel(const float* __restrict__ x,
           const float* __restrict__ W1, const float* __restrict__ B1,
           const float* __restrict__ W2, const float* __restrict__ B2,
           const float* __restrict__ Wc1, const float* __restrict__ Bc1,
           const float* __restrict__ Wc2,
           float* __restrict__ out, int nrows)
{
    // Lane -> agent mapping: warp covers a contiguous 32-agent half-ring.
    int lane = threadIdx.x & 31;
    int seg  = (threadIdx.x >> 5) & 1;   // which half of the ring
    int rpar = (threadIdx.x >> 6);       // row parity within the block
    int n    = seg * 32 + lane;
    int nxt  = (n + 1) & 63;
    int prv  = (n + 63) & 63;

    // This lane's intrinsic weights live in REGISTERS for the whole kernel.
    float w1[HW], b1[HW], w2[HW];
    {
        const float4* pW1 = (const float4*)(W1 + n * HW);
        const float4* pB1 = (const float4*)(B1 + n * HW);
        const float4* pW2 = (const float4*)(W2 + n * HW);
        float4 a, b;
        a = pW1[0]; b = pW1[1];
        w1[0]=a.x; w1[1]=a.y; w1[2]=a.z; w1[3]=a.w; w1[4]=b.x; w1[5]=b.y; w1[6]=b.z; w1[7]=b.w;
        a = pB1[0]; b = pB1[1];
        b1[0]=a.x; b1[1]=a.y; b1[2]=a.z; b1[3]=a.w; b1[4]=b.x; b1[5]=b.y; b1[6]=b.z; b1[7]=b.w;
        a = pW2[0]; b = pW2[1];
        w2[0]=a.x; w2[1]=a.y; w2[2]=a.z; w2[3]=a.w; w2[4]=b.x; w2[5]=b.y; w2[6]=b.z; w2[7]=b.w;
    }
    float b2 = B2[n];

    // Coupling constants: packed h-pairs built per thread at init (uniform loads).
    half2 A0[4], A1[4], CB[4];
    float CW[8];
    #pragma unroll
    for (int p = 0; p < 4; p++) {
        A0[p] = __floats2half2_rn(Wc1[2*p],     Wc1[2*p + 1]);     // weight on x_send
        A1[p] = __floats2half2_rn(Wc1[8 + 2*p], Wc1[8 + 2*p + 1]); // weight on x_recv
        CB[p] = __floats2half2_rn(Bc1[2*p],     Bc1[2*p + 1]);
        CW[2*p]     = Wc2[2*p];
        CW[2*p + 1] = Wc2[2*p + 1];
    }

    int r0 = blockIdx.x * RPB;
    #pragma unroll 2
    for (int r = r0 + rpar; r < r0 + RPB && r < nrows; r += 2) {
        const float* xrow = x + (size_t)r * N_AG;
        float xc = xrow[n];     // coalesced: lane n -> column n
        float xn = xrow[nxt];   // same row shifted by 1: L1 hit

        half2 xch = __float2half2_rn(xc);

        // contrib[n] = g(x[n], x[n+1])
        float contrib = coup(xch, __float2half2_rn(xn), A0, A1, CB, CW);

        // contrib[n-1] from the neighbor lane; warp-seam lane recomputes.
        float cl = __shfl_up_sync(0xffffffffu, contrib, 1);
        if (lane == 0) {
            float xp = xrow[prv];
            cl = coup(__float2half2_rn(xp), xch, A0, A1, CB, CW);
        }

        // intrinsic per-agent MLP: fp32 pre-act + dot, f16x2 tanh, register weights
        float acc = b2;
        float2 f;
        f = tanh_pair(fmaf(xc, w1[0], b1[0]), fmaf(xc, w1[1], b1[1]));
        acc = fmaf(f.x, w2[0], fmaf(f.y, w2[1], acc));
        f = tanh_pair(fmaf(xc, w1[2], b1[2]), fmaf(xc, w1[3], b1[3]));
        acc = fmaf(f.x, w2[2], fmaf(f.y, w2[3], acc));
        f = tanh_pair(fmaf(xc, w1[4], b1[4]), fmaf(xc, w1[5], b1[5]));
        acc = fmaf(f.x, w2[4], fmaf(f.y, w2[5], acc));
        f = tanh_pair(fmaf(xc, w1[6], b1[6]), fmaf(xc, w1[7], b1[7]));
        acc = fmaf(f.x, w2[6], fmaf(f.y, w2[7], acc));

        out[(size_t)r * N_AG + n] = acc + cl - contrib;   // coalesced store
    }
}

extern "C" void kernel_launch(void* const* d_in, const int* in_sizes, int n_in,
                              void* d_out, int out_size)
{
    // metadata order: x, W1, b1, W2, b2, Wc1, bc1, Wc2, bc2, send_idx, recv_idx
    const float* x = (const float*)d_in[0];
    float* out = (float*)d_out;

    int nrows = in_sizes[0] / N_AG;
    int grid = (nrows + RPB - 1) / RPB;
    ode_kernel<<<grid, BLK>>>(x,
                              (const float*)d_in[1], (const float*)d_in[2],
                              (const float*)d_in[3], (const float*)d_in[4],
                              (const float*)d_in[5], (const float*)d_in[6],
                              (const float*)d_in[7],
                              out, nrows);
}

// round 8
// speedup vs baseline: 2.0317x; 2.0317x over previous
#include <cuda_runtime.h>
#include <cuda_fp16.h>

#define N_AG 64
#define HW 8
#define BLK 128
#define SEG_AG 16          // agents per thread (quarter-ring segment)

__device__ __forceinline__ half2 tanh_h2(half2 x) {
    half2 y;
    asm("tanh.approx.f16x2 %0, %1;"
        : "=r"(reinterpret_cast<unsigned&>(y))
        : "r"(reinterpret_cast<unsigned const&>(x)));
    return y;
}

// fp32 tanh-pair via one f16x2 MUFU (fp32 pre-act, packed tanh)
__device__ __forceinline__ float2 tanh_pair(float a, float b) {
    return __half22float2(tanh_h2(__floats2half2_rn(a, b)));
}

// Coupling for one edge: HFMA2 pre-activation on h-paired weights, fp32 dot.
__device__ __forceinline__ float coup(half2 s2, half2 n2,
                                      const half2* A0, const half2* A1,
                                      const half2* CB, const float* CW)
{
    float cc = 0.f;
    #pragma unroll
    for (int p = 0; p < 4; p++) {
        half2 t = __hfma2(s2, A0[p], __hfma2(n2, A1[p], CB[p]));
        float2 g = __half22float2(tanh_h2(t));
        cc = fmaf(g.x, CW[2*p], fmaf(g.y, CW[2*p + 1], cc));
    }
    return cc;
}

__global__ void __launch_bounds__(BLK)
ode_kernel(const float* __restrict__ x,
           const float* __restrict__ W1, const float* __restrict__ B1,
           const float* __restrict__ W2, const float* __restrict__ B2,
           const float* __restrict__ Wc1, const float* __restrict__ Bc1,
           const float* __restrict__ Wc2,
           float* __restrict__ out, int nrows, int rstride)
{
    // Per-agent weights in shared: uniform-broadcast LDS.128, each read
    // amortized over TWO rows per thread.
    __shared__ float4 sW1[N_AG * 2], sB1[N_AG * 2], sW2[N_AG * 2];
    __shared__ float  sB2[N_AG];

    int tid = threadIdx.x;
    sW1[tid] = ((const float4*)W1)[tid];
    sB1[tid] = ((const float4*)B1)[tid];
    sW2[tid] = ((const float4*)W2)[tid];
    if (tid < N_AG) sB2[tid] = B2[tid];

    // Coupling constants packed per thread (uniform loads, L1-cached)
    half2 A0[4], A1[4], CB[4];
    float CW[8];
    #pragma unroll
    for (int p = 0; p < 4; p++) {
        A0[p] = __floats2half2_rn(Wc1[2*p],     Wc1[2*p + 1]);     // x_send w
        A1[p] = __floats2half2_rn(Wc1[8 + 2*p], Wc1[8 + 2*p + 1]); // x_recv w
        CB[p] = __floats2half2_rn(Bc1[2*p],     Bc1[2*p + 1]);
        CW[2*p]     = Wc2[2*p];
        CW[2*p + 1] = Wc2[2*p + 1];
    }
    __syncthreads();

    int rowA = (blockIdx.x >> 2) * BLK + tid;  // block-uniform segment keeps
    int seg  = blockIdx.x & 3;                 // weight indices warp-uniform
    if (rowA >= rstride) return;
    int rowB = rowA + rstride;
    if (rowB >= nrows) rowB = rowA;            // odd-tail: duplicate (safe, deterministic)

    const float* xrowA = x + (size_t)rowA * N_AG;
    const float* xrowB = x + (size_t)rowB * N_AG;
    int n0 = seg * SEG_AG;

    const float4* xrA = (const float4*)xrowA + (n0 >> 2);
    const float4* xrB = (const float4*)xrowB + (n0 >> 2);
    float4* outA = (float4*)(out + (size_t)rowA * N_AG) + (n0 >> 2);
    float4* outB = (float4*)(out + (size_t)rowB * N_AG) + (n0 >> 2);

    float xPrevA = xrowA[(n0 + 63) & 63],  xNextA = xrowA[(n0 + SEG_AG) & 63];
    float xPrevB = xrowB[(n0 + 63) & 63],  xNextB = xrowB[(n0 + SEG_AG) & 63];

    float4 curA = xrA[0], curB = xrB[0];

    // interactions[n] = contrib[n-1] - contrib[n]; seed carries with contrib[n0-1]
    half2 nhA = __float2half2_rn(curA.x);
    half2 nhB = __float2half2_rn(curB.x);
    float cprevA = coup(__float2half2_rn(xPrevA), nhA, A0, A1, CB, CW);
    float cprevB = coup(__float2half2_rn(xPrevB), nhB, A0, A1, CB, CW);

    #pragma unroll
    for (int c = 0; c < 4; c++) {
        float4 nxtA, nxtB;
        float nA0, nB0;
        if (c < 3) { nxtA = xrA[c+1]; nxtB = xrB[c+1]; nA0 = nxtA.x; nB0 = nxtB.x; }
        else       { nA0 = xNextA; nB0 = xNextB; }

        float xvA[5] = {curA.x, curA.y, curA.z, curA.w, nA0};
        float xvB[5] = {curB.x, curB.y, curB.z, curB.w, nB0};

        float resA[4], resB[4];
        #pragma unroll
        for (int j = 0; j < 4; j++) {
            int n = n0 + c * 4 + j;

            // one set of weight LDS serves BOTH rows
            float4 w1a = sW1[n*2], w1b = sW1[n*2+1];
            float4 b1a = sB1[n*2], b1b = sB1[n*2+1];
            float4 w2a = sW2[n*2], w2b = sW2[n*2+1];
            float  bb2 = sB2[n];

            // ---- row A ----
            {
                half2 sh = nhA; nhA = __float2half2_rn(xvA[j + 1]);
                float cc = coup(sh, nhA, A0, A1, CB, CW);
                float xs = xvA[j];
                float acc = bb2;
                float2 f;
                f = tanh_pair(fmaf(xs, w1a.x, b1a.x), fmaf(xs, w1a.y, b1a.y));
                acc = fmaf(f.x, w2a.x, fmaf(f.y, w2a.y, acc));
                f = tanh_pair(fmaf(xs, w1a.z, b1a.z), fmaf(xs, w1a.w, b1a.w));
                acc = fmaf(f.x, w2a.z, fmaf(f.y, w2a.w, acc));
                f = tanh_pair(fmaf(xs, w1b.x, b1b.x), fmaf(xs, w1b.y, b1b.y));
                acc = fmaf(f.x, w2b.x, fmaf(f.y, w2b.y, acc));
                f = tanh_pair(fmaf(xs, w1b.z, b1b.z), fmaf(xs, w1b.w, b1b.w));
                acc = fmaf(f.x, w2b.z, fmaf(f.y, w2b.w, acc));
                resA[j] = acc + cprevA - cc;
                cprevA = cc;
            }
            // ---- row B ----
            {
                half2 sh = nhB; nhB = __float2half2_rn(xvB[j + 1]);
                float cc = coup(sh, nhB, A0, A1, CB, CW);
                float xs = xvB[j];
                float acc = bb2;
                float2 f;
                f = tanh_pair(fmaf(xs, w1a.x, b1a.x), fmaf(xs, w1a.y, b1a.y));
                acc = fmaf(f.x, w2a.x, fmaf(f.y, w2a.y, acc));
                f = tanh_pair(fmaf(xs, w1a.z, b1a.z), fmaf(xs, w1a.w, b1a.w));
                acc = fmaf(f.x, w2a.z, fmaf(f.y, w2a.w, acc));
                f = tanh_pair(fmaf(xs, w1b.x, b1b.x), fmaf(xs, w1b.y, b1b.y));
                acc = fmaf(f.x, w2b.x, fmaf(f.y, w2b.y, acc));
                f = tanh_pair(fmaf(xs, w1b.z, b1b.z), fmaf(xs, w1b.w, b1b.w));
                acc = fmaf(f.x, w2b.z, fmaf(f.y, w2b.w, acc));
                resB[j] = acc + cprevB - cc;
                cprevB = cc;
            }
        }

        float4 oA, oB;
        oA.x = resA[0]; oA.y = resA[1]; oA.z = resA[2]; oA.w = resA[3];
        oB.x = resB[0]; oB.y = resB[1]; oB.z = resB[2]; oB.w = resB[3];
        outA[c] = oA;
        outB[c] = oB;
        if (c < 3) { curA = nxtA; curB = nxtB; }
    }
}

extern "C" void kernel_launch(void* const* d_in, const int* in_sizes, int n_in,
                              void* d_out, int out_size)
{
    // metadata order: x, W1, b1, W2, b2, Wc1, bc1, Wc2, bc2, send_idx, recv_idx
    const float* x = (const float*)d_in[0];
    float* out = (float*)d_out;

    int nrows = in_sizes[0] / N_AG;
    int rstride = (nrows + 1) / 2;                 // rows per half-split
    int rowBlocks = (rstride + BLK - 1) / BLK;
    int grid = rowBlocks * 4;                      // 4 ring segments
    ode_kernel<<<grid, BLK>>>(x,
                              (const float*)d_in[1], (const float*)d_in[2],
                              (const float*)d_in[3], (const float*)d_in[4],
                              (const float*)d_in[5], (const float*)d_in[6],
                              (const float*)d_in[7],
                              out, nrows, rstride);
}